// round 6
// baseline (speedup 1.0000x reference)
#include <cuda_runtime.h>
#include <math.h>

#define BMAX 65536

// ---- scratch (allocation-free rule: __device__ globals) ----
__device__ __align__(16) float g_bufA[(size_t)BMAX * 17 * 64];
__device__ __align__(16) float g_bufB[(size_t)BMAX * 17 * 64];
__device__ __align__(16) float g_z[(size_t)BMAX * 256];
__device__ __align__(16) float g_emb[(size_t)BMAX * 128];
__device__ double g_stats[68];   // [set*34 + 2*node + {sum, sumsq}]
__device__ float g_scale1[17], g_shift1[17], g_scale2[17], g_shift2[17];

// ---- adjacency tables (I + A_norm): neighbor lists + uniform weight per node ----
__constant__ int   c_cnt[17] = {2,0,0,0,0,4,4,2,2,1,1,3,3,2,2,1,1};
__constant__ float c_w[17]   = {0.5f,0.f,0.f,0.f,0.f,0.25f,0.25f,0.5f,0.5f,1.f,1.f,
                                (1.f/3.f),(1.f/3.f),0.5f,0.5f,1.f,1.f};
__constant__ int   c_nb[17][4] = {
    {5,6,0,0},  {0,0,0,0}, {0,0,0,0}, {0,0,0,0}, {0,0,0,0},
    {7,6,11,0}, {8,5,12,0},
    {5,9,0,0},  {6,10,0,0},
    {7,0,0,0},  {8,0,0,0},
    {5,12,13,0},{6,11,14,0},
    {11,15,0,0},{12,16,0,0},
    {13,0,0,0}, {14,0,0,0}
};

__global__ void k_zero() {
    if (threadIdx.x < 68) g_stats[threadIdx.x] = 0.0;
}

// ---- encoder: h[row, c] = relu(x[row,0]*W[0,c] + x[row,1]*W[1,c] + b[c]) ----
__global__ void __launch_bounds__(256)
k_enc(const float* __restrict__ x, const float* __restrict__ W,
      const float* __restrict__ b, int M17) {
    int idx = blockIdx.x * 256 + threadIdx.x;
    if (idx >= M17 * 16) return;
    int row = idx >> 4, c4 = idx & 15;
    float x0 = __ldg(x + (size_t)row * 2);
    float x1 = __ldg(x + (size_t)row * 2 + 1);
    float4 w0 = *(const float4*)(W + c4 * 4);
    float4 w1 = *(const float4*)(W + 64 + c4 * 4);
    float4 bb = *(const float4*)(b + c4 * 4);
    float4 v;
    v.x = fmaxf(fmaf(x0, w0.x, fmaf(x1, w1.x, bb.x)), 0.f);
    v.y = fmaxf(fmaf(x0, w0.y, fmaf(x1, w1.y, bb.y)), 0.f);
    v.z = fmaxf(fmaf(x0, w0.z, fmaf(x1, w1.z, bb.z)), 0.f);
    v.w = fmaxf(fmaf(x0, w0.w, fmaf(x1, w1.w, bb.w)), 0.f);
    *(float4*)(g_bufB + (size_t)row * 64 + c4 * 4) = v;
}

// ---- aggregation: y = h + A_norm @ h (per sample). g_bufB -> g_bufA ----
__global__ void __launch_bounds__(256)
k_agg(int M17) {
    int idx = blockIdx.x * 256 + threadIdx.x;
    if (idx >= M17 * 16) return;
    int row = idx >> 4, c4 = idx & 15;
    int n = row % 17;
    size_t base = (size_t)(row - n) * 64 + c4 * 4;
    float4 acc = *(const float4*)(g_bufB + (size_t)row * 64 + c4 * 4);
    int cnt = c_cnt[n];
    float w = c_w[n];
    for (int j = 0; j < cnt; j++) {
        const float4 hb = *(const float4*)(g_bufB + base + (size_t)c_nb[n][j] * 64);
        acc.x = fmaf(w, hb.x, acc.x);
        acc.y = fmaf(w, hb.y, acc.y);
        acc.z = fmaf(w, hb.z, acc.z);
        acc.w = fmaf(w, hb.w, acc.w);
    }
    *(float4*)(g_bufA + (size_t)row * 64 + c4 * 4) = acc;
}

// ---- per-node sum/sumsq over g_bufA. 128 rows/block, 2 threads/row ----
__global__ void __launch_bounds__(256)
k_stats(int set) {
    __shared__ float ss[17], qq[17];
    int tid = threadIdx.x;
    if (tid < 17) { ss[tid] = 0.f; qq[tid] = 0.f; }
    __syncthreads();
    int row = blockIdx.x * 128 + (tid >> 1);
    int half = tid & 1;
    const float4* p = (const float4*)(g_bufA + (size_t)row * 64 + half * 32);
    float s = 0.f, q = 0.f;
#pragma unroll
    for (int i = 0; i < 8; i++) {
        float4 v = p[i];
        s += v.x + v.y + v.z + v.w;
        q = fmaf(v.x, v.x, fmaf(v.y, v.y, fmaf(v.z, v.z, fmaf(v.w, v.w, q))));
    }
    int node = row % 17;
    atomicAdd(&ss[node], s);
    atomicAdd(&qq[node], q);
    __syncthreads();
    if (tid < 17) {
        atomicAdd(&g_stats[set * 34 + 2 * tid], (double)ss[tid]);
        atomicAdd(&g_stats[set * 34 + 2 * tid + 1], (double)qq[tid]);
    }
}

// ---- finalize BN stats -> fused scale/shift ----
__global__ void k_fin(const float* __restrict__ gamma, const float* __restrict__ beta,
                      double invN, int set) {
    int i = threadIdx.x;
    if (i >= 17) return;
    double s = g_stats[set * 34 + 2 * i];
    double q = g_stats[set * 34 + 2 * i + 1];
    double mean = s * invN;
    double var = q * invN - mean * mean;
    if (var < 0.0) var = 0.0;
    float inv = (float)(1.0 / sqrt(var + 1e-5));
    float sc = gamma[i] * inv;
    float sh = beta[i] - (float)mean * sc;
    if (set == 0) { g_scale1[i] = sc; g_shift1[i] = sh; }
    else          { g_scale2[i] = sc; g_shift2[i] = sh; }
}

// ---- tiled fp32 GEMM: C = act(affine(A) @ W + bias) ----
// BM=128, BN=64, BK=32; 256 threads; 8x4 register tile; ~26KB smem.
// Requires M%128==0, N%64==0, K%32==0. W is (K,N) row-major.
template <int RELU, int AFF>
__global__ void __launch_bounds__(256)
k_gemm(const float* __restrict__ A, const float* __restrict__ W,
       const float* __restrict__ bias, float* __restrict__ C,
       int M, int N, int K) {
    __shared__ float As[128 * 36];   // padded stride 36
    __shared__ float Bs[32 * 64];
    int tid = threadIdx.x;
    int tx = tid & 15, ty = tid >> 4;
    int m0 = blockIdx.x * 128;
    int n0 = blockIdx.y * 64;

    float acc[8][4];
    float4 bb = *(const float4*)(bias + n0 + tx * 4);
#pragma unroll
    for (int r = 0; r < 8; r++) {
        acc[r][0] = bb.x; acc[r][1] = bb.y; acc[r][2] = bb.z; acc[r][3] = bb.w;
    }

    for (int kc = 0; kc < K; kc += 32) {
        // A tile: 128 rows x 32 k
#pragma unroll
        for (int i = 0; i < 4; i++) {
            int t4 = tid + i * 256;
            int row = t4 >> 3, k4 = t4 & 7;
            float4 v = *(const float4*)(A + (size_t)(m0 + row) * K + kc + k4 * 4);
            if (AFF != 0) {
                int node = (m0 + row) % 17;
                float sc = (AFF == 1) ? g_scale1[node] : g_scale2[node];
                float sh = (AFF == 1) ? g_shift1[node] : g_shift2[node];
                v.x = fmaf(v.x, sc, sh);
                v.y = fmaf(v.y, sc, sh);
                v.z = fmaf(v.z, sc, sh);
                v.w = fmaf(v.w, sc, sh);
            }
            *(float4*)&As[row * 36 + k4 * 4] = v;
        }
        // B tile: 32 k x 64 n
#pragma unroll
        for (int i = 0; i < 2; i++) {
            int t4 = tid + i * 256;
            int k = t4 >> 4, n4 = t4 & 15;
            *(float4*)&Bs[k * 64 + n4 * 4] =
                *(const float4*)(W + (size_t)(kc + k) * N + n0 + n4 * 4);
        }
        __syncthreads();
#pragma unroll
        for (int k = 0; k < 32; k += 4) {
            float4 b0 = *(float4*)&Bs[(k + 0) * 64 + tx * 4];
            float4 b1 = *(float4*)&Bs[(k + 1) * 64 + tx * 4];
            float4 b2 = *(float4*)&Bs[(k + 2) * 64 + tx * 4];
            float4 b3 = *(float4*)&Bs[(k + 3) * 64 + tx * 4];
#pragma unroll
            for (int r = 0; r < 8; r++) {
                float4 a = *(float4*)&As[(ty * 8 + r) * 36 + k];
                acc[r][0] = fmaf(a.x, b0.x, acc[r][0]);
                acc[r][1] = fmaf(a.x, b0.y, acc[r][1]);
                acc[r][2] = fmaf(a.x, b0.z, acc[r][2]);
                acc[r][3] = fmaf(a.x, b0.w, acc[r][3]);
                acc[r][0] = fmaf(a.y, b1.x, acc[r][0]);
                acc[r][1] = fmaf(a.y, b1.y, acc[r][1]);
                acc[r][2] = fmaf(a.y, b1.z, acc[r][2]);
                acc[r][3] = fmaf(a.y, b1.w, acc[r][3]);
                acc[r][0] = fmaf(a.z, b2.x, acc[r][0]);
                acc[r][1] = fmaf(a.z, b2.y, acc[r][1]);
                acc[r][2] = fmaf(a.z, b2.z, acc[r][2]);
                acc[r][3] = fmaf(a.z, b2.w, acc[r][3]);
                acc[r][0] = fmaf(a.w, b3.x, acc[r][0]);
                acc[r][1] = fmaf(a.w, b3.y, acc[r][1]);
                acc[r][2] = fmaf(a.w, b3.z, acc[r][2]);
                acc[r][3] = fmaf(a.w, b3.w, acc[r][3]);
            }
        }
        __syncthreads();
    }

#pragma unroll
    for (int r = 0; r < 8; r++) {
        float4 v;
        v.x = acc[r][0]; v.y = acc[r][1]; v.z = acc[r][2]; v.w = acc[r][3];
        if (RELU != 0) {
            v.x = fmaxf(v.x, 0.f); v.y = fmaxf(v.y, 0.f);
            v.z = fmaxf(v.z, 0.f); v.w = fmaxf(v.w, 0.f);
        }
        *(float4*)(C + (size_t)(m0 + ty * 8 + r) * N + n0 + tx * 4) = v;
    }
}

// ---- L2 normalize: warp per row of 128 ----
__global__ void __launch_bounds__(256)
k_norm(float* __restrict__ out, int B) {
    int w = (blockIdx.x * blockDim.x + threadIdx.x) >> 5;
    int l = threadIdx.x & 31;
    if (w >= B) return;
    float4 v = ((const float4*)(g_emb + (size_t)w * 128))[l];
    float ss = v.x * v.x + v.y * v.y + v.z * v.z + v.w * v.w;
#pragma unroll
    for (int off = 16; off > 0; off >>= 1)
        ss += __shfl_xor_sync(0xffffffffu, ss, off);
    float scl = 1.f / fmaxf(sqrtf(ss), 1e-12f);
    float4 o;
    o.x = v.x * scl; o.y = v.y * scl; o.z = v.z * scl; o.w = v.w * scl;
    ((float4*)out)[(size_t)w * 32 + l] = o;
}

extern "C" void kernel_launch(void* const* d_in, const int* in_sizes, int n_in,
                              void* d_out, int out_size) {
    const float* x      = (const float*)d_in[0];
    const float* W_enc  = (const float*)d_in[1];
    const float* b_enc  = (const float*)d_in[2];
    const float* W_gc1  = (const float*)d_in[3];
    const float* b_gc1  = (const float*)d_in[4];
    const float* W_gc2  = (const float*)d_in[5];
    const float* b_gc2  = (const float*)d_in[6];
    const float* gamma1 = (const float*)d_in[7];
    const float* beta1  = (const float*)d_in[8];
    const float* gamma2 = (const float*)d_in[9];
    const float* beta2  = (const float*)d_in[10];
    const float* W_p1   = (const float*)d_in[11];
    const float* b_p1   = (const float*)d_in[12];
    const float* W_p2   = (const float*)d_in[13];
    const float* b_p2   = (const float*)d_in[14];
    float* out = (float*)d_out;

    // CRITICAL FIX: resolve device addresses of __device__ globals. Passing the
    // symbol directly from host code passes the host shadow address (garbage).
    float *bufA = 0, *bufB = 0, *z = 0, *emb = 0;
    cudaGetSymbolAddress((void**)&bufA, g_bufA);
    cudaGetSymbolAddress((void**)&bufB, g_bufB);
    cudaGetSymbolAddress((void**)&z,    g_z);
    cudaGetSymbolAddress((void**)&emb,  g_emb);

    int B = in_sizes[0] / 34;        // x is (B,17,2)
    if (B <= 0) return;
    int M17 = B * 17;
    int gEl = (M17 * 16 + 255) / 256;
    double invN = 1.0 / ((double)B * 64.0);

    k_zero<<<1, 68>>>();
    // encoder -> h1 (g_bufB)
    k_enc<<<gEl, 256>>>(x, W_enc, b_enc, M17);
    // y1 = h1 + agg(h1) -> g_bufA ; BN1 stats
    k_agg<<<gEl, 256>>>(M17);
    k_stats<<<M17 / 128, 256>>>(0);
    k_fin<<<1, 32>>>(gamma1, beta1, invN, 0);
    // gc1: h2 = relu(bn1(y1) @ W_gc1 + b) -> g_bufB
    k_gemm<1, 1><<<dim3(M17 / 128, 1), 256>>>(bufA, W_gc1, b_gc1, bufB, M17, 64, 64);
    // y2 = h2 + agg(h2) -> g_bufA ; BN2 stats
    k_agg<<<gEl, 256>>>(M17);
    k_stats<<<M17 / 128, 256>>>(1);
    k_fin<<<1, 32>>>(gamma2, beta2, invN, 1);
    // gc2: pooled = relu(bn2(y2) @ W_gc2 + b) -> g_bufB (B,1088)
    k_gemm<1, 2><<<dim3(M17 / 128, 1), 256>>>(bufA, W_gc2, b_gc2, bufB, M17, 64, 64);
    // p1: z = relu(pooled @ W_p1 + b_p1) -> g_z (B,256)
    k_gemm<1, 0><<<dim3(B / 128, 4), 256>>>(bufB, W_p1, b_p1, z, B, 256, 1088);
    // p2: emb = z @ W_p2 + b_p2 -> g_emb (B,128)
    k_gemm<0, 0><<<dim3(B / 128, 2), 256>>>(z, W_p2, b_p2, emb, B, 128, 256);
    k_norm<<<(B * 32 + 255) / 256, 256>>>(out, B);
}

// round 7
// speedup vs baseline: 1.0052x; 1.0052x over previous
#include <cuda_runtime.h>
#include <math.h>

#define BMAX 65536

// ---- scratch (allocation-free rule: __device__ globals) ----
__device__ __align__(16) float g_bufA[(size_t)BMAX * 17 * 64];
__device__ __align__(16) float g_bufB[(size_t)BMAX * 17 * 64];
__device__ __align__(16) float g_z[(size_t)BMAX * 256];
__device__ double g_stats[68];   // [set*34 + 2*node + {sum, sumsq}]
__device__ float g_scale1[17], g_shift1[17], g_scale2[17], g_shift2[17];

// ---- adjacency tables (I + A_norm) ----
__constant__ int   c_cnt[17] = {2,0,0,0,0,4,4,2,2,1,1,3,3,2,2,1,1};
__constant__ float c_w[17]   = {0.5f,0.f,0.f,0.f,0.f,0.25f,0.25f,0.5f,0.5f,1.f,1.f,
                                (1.f/3.f),(1.f/3.f),0.5f,0.5f,1.f,1.f};
__constant__ int   c_nb[17][4] = {
    {5,6,0,0},  {0,0,0,0}, {0,0,0,0}, {0,0,0,0}, {0,0,0,0},
    {7,6,11,0}, {8,5,12,0},
    {5,9,0,0},  {6,10,0,0},
    {7,0,0,0},  {8,0,0,0},
    {5,12,13,0},{6,11,14,0},
    {11,15,0,0},{12,16,0,0},
    {13,0,0,0}, {14,0,0,0}
};

// ---- f32x2 helpers ----
typedef unsigned long long ull;
__device__ __forceinline__ ull pack2(float x, float y) {
    ull r; asm("mov.b64 %0, {%1,%2};" : "=l"(r) : "f"(x), "f"(y)); return r;
}
__device__ __forceinline__ void unpack2(ull v, float &x, float &y) {
    asm("mov.b64 {%0,%1}, %2;" : "=f"(x), "=f"(y) : "l"(v));
}
__device__ __forceinline__ void fma2(ull &d, ull a, ull b) {
    asm("fma.rn.f32x2 %0, %1, %2, %3;" : "=l"(d) : "l"(a), "l"(b), "l"(d));
}

__global__ void k_zero() {
    if (threadIdx.x < 68) g_stats[threadIdx.x] = 0.0;
}

// ---- fused elementwise: (optional encoder) + aggregation + BN stats ----
// Block = 256 threads, 8 samples. ENC=1: src=x, compute h; ENC=0: src=h (B,17,64).
// Writes y = h + A_norm@h to ydst, accumulates per-node sum/sumsq into g_stats[set].
template <int ENC>
__global__ void __launch_bounds__(256)
k_fuse(const float* __restrict__ src, const float* __restrict__ W,
       const float* __restrict__ bvec, float* __restrict__ ydst, int B, int set) {
    __shared__ float h_sm[8 * 1156];      // [s][node*68 + c], padded stride 68
    __shared__ float ss[17], qq[17];
    int tid = threadIdx.x;
    int s0 = blockIdx.x * 8;
    if (tid < 17) { ss[tid] = 0.f; qq[tid] = 0.f; }

    // phase 1: materialize h in smem
    for (int idx = tid; idx < 272; idx += 256) {
        int n = idx >> 4, c4 = idx & 15;
        float4 w0, w1, bb;
        if (ENC) {
            w0 = *(const float4*)(W + c4 * 4);
            w1 = *(const float4*)(W + 64 + c4 * 4);
            bb = *(const float4*)(bvec + c4 * 4);
        }
#pragma unroll
        for (int s = 0; s < 8; s++) {
            int e = s0 + s;
            if (e >= B) break;
            float4 v;
            if (ENC) {
                float x0 = src[((size_t)e * 17 + n) * 2];
                float x1 = src[((size_t)e * 17 + n) * 2 + 1];
                v.x = fmaxf(fmaf(x0, w0.x, fmaf(x1, w1.x, bb.x)), 0.f);
                v.y = fmaxf(fmaf(x0, w0.y, fmaf(x1, w1.y, bb.y)), 0.f);
                v.z = fmaxf(fmaf(x0, w0.z, fmaf(x1, w1.z, bb.z)), 0.f);
                v.w = fmaxf(fmaf(x0, w0.w, fmaf(x1, w1.w, bb.w)), 0.f);
            } else {
                v = *(const float4*)(src + ((size_t)e * 17 + n) * 64 + c4 * 4);
            }
            *(float4*)&h_sm[s * 1156 + n * 68 + c4 * 4] = v;
        }
    }
    __syncthreads();

    // phase 2: aggregate + write y + stats
    for (int idx = tid; idx < 272; idx += 256) {
        int n = idx >> 4, c4 = idx & 15;
        float w = c_w[n];
        int cnt = c_cnt[n];
        float sp = 0.f, qp = 0.f;
#pragma unroll
        for (int s = 0; s < 8; s++) {
            int e = s0 + s;
            if (e >= B) break;
            float4 acc = *(const float4*)&h_sm[s * 1156 + n * 68 + c4 * 4];
            for (int j = 0; j < cnt; j++) {
                const float4 hb = *(const float4*)&h_sm[s * 1156 + c_nb[n][j] * 68 + c4 * 4];
                acc.x = fmaf(w, hb.x, acc.x);
                acc.y = fmaf(w, hb.y, acc.y);
                acc.z = fmaf(w, hb.z, acc.z);
                acc.w = fmaf(w, hb.w, acc.w);
            }
            *(float4*)(ydst + ((size_t)e * 17 + n) * 64 + c4 * 4) = acc;
            sp += acc.x + acc.y + acc.z + acc.w;
            qp = fmaf(acc.x, acc.x, fmaf(acc.y, acc.y, fmaf(acc.z, acc.z, fmaf(acc.w, acc.w, qp))));
        }
        atomicAdd(&ss[n], sp);
        atomicAdd(&qq[n], qp);
    }
    __syncthreads();
    if (tid < 17) {
        atomicAdd(&g_stats[set * 34 + 2 * tid], (double)ss[tid]);
        atomicAdd(&g_stats[set * 34 + 2 * tid + 1], (double)qq[tid]);
    }
}

// ---- finalize BN stats -> fused scale/shift ----
__global__ void k_fin(const float* __restrict__ gamma, const float* __restrict__ beta,
                      double invN, int set) {
    int i = threadIdx.x;
    if (i >= 17) return;
    double s = g_stats[set * 34 + 2 * i];
    double q = g_stats[set * 34 + 2 * i + 1];
    double mean = s * invN;
    double var = q * invN - mean * mean;
    if (var < 0.0) var = 0.0;
    float inv = (float)(1.0 / sqrt(var + 1e-5));
    float sc = gamma[i] * inv;
    float sh = beta[i] - (float)mean * sc;
    if (set == 0) { g_scale1[i] = sc; g_shift1[i] = sh; }
    else          { g_scale2[i] = sc; g_shift2[i] = sh; }
}

// ---- f32x2 GEMM, BN=64 (gc layers): C = relu(affine(A) @ W + bias) ----
// BM=128, BK=32; 256 threads; thread tile 8 rows (4 M-pairs) x 4 cols.
// As k-major [32][130]; Bs duplicated [32][128]. M%128==0, K%32==0, N==64.
template <int AFF>
__global__ void __launch_bounds__(256)
k_gemm64(const float* __restrict__ A, const float* __restrict__ W,
         const float* __restrict__ bias, float* __restrict__ C,
         int M, int N, int K) {
    __shared__ float As[32 * 130];
    __shared__ float Bs[32 * 128];
    int tid = threadIdx.x;
    int tx = tid & 15, ty = tid >> 4;
    size_t m0 = (size_t)blockIdx.x * 128;
    int n0 = blockIdx.y * 64;

    ull acc[4][4];
#pragma unroll
    for (int j = 0; j < 4; j++) {
        float bv = bias[n0 + tx + 16 * j];
        ull pk = pack2(bv, bv);
#pragma unroll
        for (int p = 0; p < 4; p++) acc[p][j] = pk;
    }

    for (int kc = 0; kc < K; kc += 32) {
        // A tile -> k-major (transposed scalar stores)
#pragma unroll
        for (int i = 0; i < 4; i++) {
            int t4 = tid + i * 256;
            int row = t4 >> 3, k4 = t4 & 7;
            float4 v = *(const float4*)(A + (m0 + row) * K + kc + k4 * 4);
            if (AFF != 0) {
                int node = (int)((m0 + row) % 17);
                float sc = (AFF == 1) ? g_scale1[node] : g_scale2[node];
                float sh = (AFF == 1) ? g_shift1[node] : g_shift2[node];
                v.x = fmaf(v.x, sc, sh); v.y = fmaf(v.y, sc, sh);
                v.z = fmaf(v.z, sc, sh); v.w = fmaf(v.w, sc, sh);
            }
            As[(k4 * 4 + 0) * 130 + row] = v.x;
            As[(k4 * 4 + 1) * 130 + row] = v.y;
            As[(k4 * 4 + 2) * 130 + row] = v.z;
            As[(k4 * 4 + 3) * 130 + row] = v.w;
        }
        // B tile -> duplicated
#pragma unroll
        for (int i = 0; i < 2; i++) {
            int t4 = tid + i * 256;
            int k = t4 >> 4, n4 = t4 & 15;
            float4 v = *(const float4*)(W + (size_t)(kc + k) * N + n0 + n4 * 4);
            float* bp = &Bs[k * 128 + n4 * 8];
            *(float2*)(bp + 0) = make_float2(v.x, v.x);
            *(float2*)(bp + 2) = make_float2(v.y, v.y);
            *(float2*)(bp + 4) = make_float2(v.z, v.z);
            *(float2*)(bp + 6) = make_float2(v.w, v.w);
        }
        __syncthreads();
#pragma unroll 8
        for (int k = 0; k < 32; k++) {
            ull a0 = *(const ull*)&As[k * 130 + ty * 8 + 0];
            ull a1 = *(const ull*)&As[k * 130 + ty * 8 + 2];
            ull a2 = *(const ull*)&As[k * 130 + ty * 8 + 4];
            ull a3 = *(const ull*)&As[k * 130 + ty * 8 + 6];
            ull b0 = *(const ull*)&Bs[k * 128 + 2 * tx + 0];
            ull b1 = *(const ull*)&Bs[k * 128 + 2 * tx + 32];
            ull b2 = *(const ull*)&Bs[k * 128 + 2 * tx + 64];
            ull b3 = *(const ull*)&Bs[k * 128 + 2 * tx + 96];
            fma2(acc[0][0], a0, b0); fma2(acc[0][1], a0, b1);
            fma2(acc[0][2], a0, b2); fma2(acc[0][3], a0, b3);
            fma2(acc[1][0], a1, b0); fma2(acc[1][1], a1, b1);
            fma2(acc[1][2], a1, b2); fma2(acc[1][3], a1, b3);
            fma2(acc[2][0], a2, b0); fma2(acc[2][1], a2, b1);
            fma2(acc[2][2], a2, b2); fma2(acc[2][3], a2, b3);
            fma2(acc[3][0], a3, b0); fma2(acc[3][1], a3, b1);
            fma2(acc[3][2], a3, b2); fma2(acc[3][3], a3, b3);
        }
        __syncthreads();
    }

#pragma unroll
    for (int p = 0; p < 4; p++) {
        size_t r0 = m0 + ty * 8 + 2 * p;
#pragma unroll
        for (int j = 0; j < 4; j++) {
            float lo, hi;
            unpack2(acc[p][j], lo, hi);
            lo = fmaxf(lo, 0.f); hi = fmaxf(hi, 0.f);
            C[r0 * N + n0 + tx + 16 * j] = lo;
            C[(r0 + 1) * N + n0 + tx + 16 * j] = hi;
        }
    }
}

// ---- f32x2 GEMM, BN=128 (pool layers): thread tile 8 rows x 8 cols, BK=16 ----
// NORM=1: fused L2-normalize over the 128-wide row, write to out (bias still added).
template <int RELU, int NORM>
__global__ void __launch_bounds__(256)
k_gemm128(const float* __restrict__ A, const float* __restrict__ W,
          const float* __restrict__ bias, float* __restrict__ C,
          int M, int N, int K) {
    __shared__ float As[16 * 130];
    __shared__ float Bs[16 * 256];
    int tid = threadIdx.x;
    int tx = tid & 15, ty = tid >> 4;
    size_t m0 = (size_t)blockIdx.x * 128;
    int n0 = blockIdx.y * 128;

    ull acc[4][8];
#pragma unroll
    for (int j = 0; j < 8; j++) {
        float bv = bias[n0 + tx + 16 * j];
        ull pk = pack2(bv, bv);
#pragma unroll
        for (int p = 0; p < 4; p++) acc[p][j] = pk;
    }

    for (int kc = 0; kc < K; kc += 16) {
        // A tile (128 rows x 16 k) -> k-major
#pragma unroll
        for (int i = 0; i < 2; i++) {
            int t4 = tid + i * 256;
            int row = t4 >> 2, k4 = t4 & 3;
            float4 v = *(const float4*)(A + (m0 + row) * K + kc + k4 * 4);
            As[(k4 * 4 + 0) * 130 + row] = v.x;
            As[(k4 * 4 + 1) * 130 + row] = v.y;
            As[(k4 * 4 + 2) * 130 + row] = v.z;
            As[(k4 * 4 + 3) * 130 + row] = v.w;
        }
        // B tile (16 k x 128 n) -> duplicated
#pragma unroll
        for (int i = 0; i < 2; i++) {
            int t4 = tid + i * 256;
            int k = t4 >> 5, n4 = t4 & 31;
            float4 v = *(const float4*)(W + (size_t)(kc + k) * N + n0 + n4 * 4);
            float* bp = &Bs[k * 256 + n4 * 8];
            *(float2*)(bp + 0) = make_float2(v.x, v.x);
            *(float2*)(bp + 2) = make_float2(v.y, v.y);
            *(float2*)(bp + 4) = make_float2(v.z, v.z);
            *(float2*)(bp + 6) = make_float2(v.w, v.w);
        }
        __syncthreads();
#pragma unroll 8
        for (int k = 0; k < 16; k++) {
            ull a0 = *(const ull*)&As[k * 130 + ty * 8 + 0];
            ull a1 = *(const ull*)&As[k * 130 + ty * 8 + 2];
            ull a2 = *(const ull*)&As[k * 130 + ty * 8 + 4];
            ull a3 = *(const ull*)&As[k * 130 + ty * 8 + 6];
#pragma unroll
            for (int j = 0; j < 8; j++) {
                ull b = *(const ull*)&Bs[k * 256 + 2 * tx + 32 * j];
                fma2(acc[0][j], a0, b);
                fma2(acc[1][j], a1, b);
                fma2(acc[2][j], a2, b);
                fma2(acc[3][j], a3, b);
            }
        }
        __syncthreads();
    }

#pragma unroll
    for (int p = 0; p < 4; p++) {
        size_t r0 = m0 + ty * 8 + 2 * p;
        float lo[8], hi[8];
#pragma unroll
        for (int j = 0; j < 8; j++) {
            unpack2(acc[p][j], lo[j], hi[j]);
            if (RELU) { lo[j] = fmaxf(lo[j], 0.f); hi[j] = fmaxf(hi[j], 0.f); }
        }
        if (NORM) {
            // reduce sum-of-squares across 16 tx lanes (within half-warp)
            float sl = 0.f, sh2 = 0.f;
#pragma unroll
            for (int j = 0; j < 8; j++) {
                sl = fmaf(lo[j], lo[j], sl);
                sh2 = fmaf(hi[j], hi[j], sh2);
            }
#pragma unroll
            for (int off = 8; off > 0; off >>= 1) {
                sl += __shfl_xor_sync(0xffffffffu, sl, off);
                sh2 += __shfl_xor_sync(0xffffffffu, sh2, off);
            }
            float il = 1.f / fmaxf(sqrtf(sl), 1e-12f);
            float ih = 1.f / fmaxf(sqrtf(sh2), 1e-12f);
#pragma unroll
            for (int j = 0; j < 8; j++) {
                C[r0 * N + n0 + tx + 16 * j] = lo[j] * il;
                C[(r0 + 1) * N + n0 + tx + 16 * j] = hi[j] * ih;
            }
        } else {
#pragma unroll
            for (int j = 0; j < 8; j++) {
                C[r0 * N + n0 + tx + 16 * j] = lo[j];
                C[(r0 + 1) * N + n0 + tx + 16 * j] = hi[j];
            }
        }
    }
}

extern "C" void kernel_launch(void* const* d_in, const int* in_sizes, int n_in,
                              void* d_out, int out_size) {
    const float* x      = (const float*)d_in[0];
    const float* W_enc  = (const float*)d_in[1];
    const float* b_enc  = (const float*)d_in[2];
    const float* W_gc1  = (const float*)d_in[3];
    const float* b_gc1  = (const float*)d_in[4];
    const float* W_gc2  = (const float*)d_in[5];
    const float* b_gc2  = (const float*)d_in[6];
    const float* gamma1 = (const float*)d_in[7];
    const float* beta1  = (const float*)d_in[8];
    const float* gamma2 = (const float*)d_in[9];
    const float* beta2  = (const float*)d_in[10];
    const float* W_p1   = (const float*)d_in[11];
    const float* b_p1   = (const float*)d_in[12];
    const float* W_p2   = (const float*)d_in[13];
    const float* b_p2   = (const float*)d_in[14];
    float* out = (float*)d_out;

    // Resolve device addresses of __device__ globals (host shadow != device ptr).
    float *bufA = 0, *bufB = 0, *z = 0;
    cudaGetSymbolAddress((void**)&bufA, g_bufA);
    cudaGetSymbolAddress((void**)&bufB, g_bufB);
    cudaGetSymbolAddress((void**)&z,    g_z);

    int B = in_sizes[0] / 34;        // x is (B,17,2)
    if (B <= 0) return;
    int M17 = B * 17;
    int gF = (B + 7) / 8;
    double invN = 1.0 / ((double)B * 64.0);

    k_zero<<<1, 68>>>();
    // enc + agg + BN1 stats -> y1 in bufA
    k_fuse<1><<<gF, 256>>>(x, W_enc, b_enc, bufA, B, 0);
    k_fin<<<1, 32>>>(gamma1, beta1, invN, 0);
    // gc1: h2 = relu(bn1(y1) @ W_gc1 + b) -> bufB
    k_gemm64<1><<<dim3(M17 / 128, 1), 256>>>(bufA, W_gc1, b_gc1, bufB, M17, 64, 64);
    // agg(h2) + BN2 stats -> y2 in bufA
    k_fuse<0><<<gF, 256>>>(bufB, 0, 0, bufA, B, 1);
    k_fin<<<1, 32>>>(gamma2, beta2, invN, 1);
    // gc2: pooled = relu(bn2(y2) @ W_gc2 + b) -> bufB (B,1088)
    k_gemm64<2><<<dim3(M17 / 128, 1), 256>>>(bufA, W_gc2, b_gc2, bufB, M17, 64, 64);
    // p1: z = relu(pooled @ W_p1 + b_p1) -> z (B,256)
    k_gemm128<1, 0><<<dim3(B / 128, 2), 256>>>(bufB, W_p1, b_p1, z, B, 256, 1088);
    // p2 + L2 normalize -> out (B,128)
    k_gemm128<0, 1><<<dim3(B / 128, 1), 256>>>(z, W_p2, b_p2, out, B, 128, 256);
}

// round 9
// speedup vs baseline: 1.5395x; 1.5314x over previous
#include <cuda_runtime.h>
#include <math.h>
#include <stdint.h>

#define BMAX 65536

// ---- scratch (allocation-free rule: __device__ globals) ----
__device__ __align__(16) float g_bufA[(size_t)BMAX * 17 * 64];
__device__ __align__(16) float g_bufB[(size_t)BMAX * 17 * 64];
__device__ __align__(16) float g_z[(size_t)BMAX * 256];
__device__ __align__(16) float g_wp1t[256 * 1088];   // W_p1^T (n-major), tf32 RNA-rounded
__device__ double g_stats[68];
__device__ float g_scale1[17], g_shift1[17], g_scale2[17], g_shift2[17];

// ---- adjacency tables (I + A_norm) ----
__constant__ int   c_cnt[17] = {2,0,0,0,0,4,4,2,2,1,1,3,3,2,2,1,1};
__constant__ float c_w[17]   = {0.5f,0.f,0.f,0.f,0.f,0.25f,0.25f,0.5f,0.5f,1.f,1.f,
                                (1.f/3.f),(1.f/3.f),0.5f,0.5f,1.f,1.f};
__constant__ int   c_nb[17][4] = {
    {5,6,0,0},  {0,0,0,0}, {0,0,0,0}, {0,0,0,0}, {0,0,0,0},
    {7,6,11,0}, {8,5,12,0},
    {5,9,0,0},  {6,10,0,0},
    {7,0,0,0},  {8,0,0,0},
    {5,12,13,0},{6,11,14,0},
    {11,15,0,0},{12,16,0,0},
    {13,0,0,0}, {14,0,0,0}
};

// ---- f32x2 helpers ----
typedef unsigned long long ull;
__device__ __forceinline__ ull pack2(float x, float y) {
    ull r; asm("mov.b64 %0, {%1,%2};" : "=l"(r) : "f"(x), "f"(y)); return r;
}
__device__ __forceinline__ void unpack2(ull v, float &x, float &y) {
    asm("mov.b64 {%0,%1}, %2;" : "=f"(x), "=f"(y) : "l"(v));
}
__device__ __forceinline__ void fma2(ull &d, ull a, ull b) {
    asm("fma.rn.f32x2 %0, %1, %2, %3;" : "=l"(d) : "l"(a), "l"(b), "l"(d));
}
__device__ __forceinline__ float rna_tf32(float v) {
    asm("cvt.rna.tf32.f32 %0, %1;" : "=f"(v) : "f"(v));
    return v;
}
__device__ __forceinline__ uint32_t s2u(const void* p) {
    uint32_t a;
    asm("{ .reg .u64 t; cvta.to.shared.u64 t, %1; cvt.u32.u64 %0, t; }" : "=r"(a) : "l"(p));
    return a;
}

__global__ void k_zero() {
    if (threadIdx.x < 68) g_stats[threadIdx.x] = 0.0;
}

// ---- transpose W_p1 (1088x256) -> g_wp1t (256x1088), tf32 RNA-rounded ----
__global__ void __launch_bounds__(256)
k_tr(const float* __restrict__ W, float* __restrict__ T) {
    int i = blockIdx.x * 256 + threadIdx.x;
    if (i >= 1088 * 256) return;
    int k = i >> 8, n = i & 255;
    T[(size_t)n * 1088 + k] = rna_tf32(W[i]);
}

// ---- fused elementwise: (optional encoder) + aggregation + BN stats ----
template <int ENC>
__global__ void __launch_bounds__(256)
k_fuse(const float* __restrict__ src, const float* __restrict__ W,
       const float* __restrict__ bvec, float* __restrict__ ydst, int B, int set) {
    __shared__ float h_sm[8 * 1156];
    __shared__ float ss[17], qq[17];
    int tid = threadIdx.x;
    int s0 = blockIdx.x * 8;
    if (tid < 17) { ss[tid] = 0.f; qq[tid] = 0.f; }

    for (int idx = tid; idx < 272; idx += 256) {
        int n = idx >> 4, c4 = idx & 15;
        float4 w0, w1, bb;
        if (ENC) {
            w0 = *(const float4*)(W + c4 * 4);
            w1 = *(const float4*)(W + 64 + c4 * 4);
            bb = *(const float4*)(bvec + c4 * 4);
        }
#pragma unroll
        for (int s = 0; s < 8; s++) {
            int e = s0 + s;
            if (e >= B) break;
            float4 v;
            if (ENC) {
                float x0 = src[((size_t)e * 17 + n) * 2];
                float x1 = src[((size_t)e * 17 + n) * 2 + 1];
                v.x = fmaxf(fmaf(x0, w0.x, fmaf(x1, w1.x, bb.x)), 0.f);
                v.y = fmaxf(fmaf(x0, w0.y, fmaf(x1, w1.y, bb.y)), 0.f);
                v.z = fmaxf(fmaf(x0, w0.z, fmaf(x1, w1.z, bb.z)), 0.f);
                v.w = fmaxf(fmaf(x0, w0.w, fmaf(x1, w1.w, bb.w)), 0.f);
            } else {
                v = *(const float4*)(src + ((size_t)e * 17 + n) * 64 + c4 * 4);
            }
            *(float4*)&h_sm[s * 1156 + n * 68 + c4 * 4] = v;
        }
    }
    __syncthreads();

    for (int idx = tid; idx < 272; idx += 256) {
        int n = idx >> 4, c4 = idx & 15;
        float w = c_w[n];
        int cnt = c_cnt[n];
        float sp = 0.f, qp = 0.f;
#pragma unroll
        for (int s = 0; s < 8; s++) {
            int e = s0 + s;
            if (e >= B) break;
            float4 acc = *(const float4*)&h_sm[s * 1156 + n * 68 + c4 * 4];
            for (int j = 0; j < cnt; j++) {
                const float4 hb = *(const float4*)&h_sm[s * 1156 + c_nb[n][j] * 68 + c4 * 4];
                acc.x = fmaf(w, hb.x, acc.x);
                acc.y = fmaf(w, hb.y, acc.y);
                acc.z = fmaf(w, hb.z, acc.z);
                acc.w = fmaf(w, hb.w, acc.w);
            }
            *(float4*)(ydst + ((size_t)e * 17 + n) * 64 + c4 * 4) = acc;
            sp += acc.x + acc.y + acc.z + acc.w;
            qp = fmaf(acc.x, acc.x, fmaf(acc.y, acc.y, fmaf(acc.z, acc.z, fmaf(acc.w, acc.w, qp))));
        }
        atomicAdd(&ss[n], sp);
        atomicAdd(&qq[n], qp);
    }
    __syncthreads();
    if (tid < 17) {
        atomicAdd(&g_stats[set * 34 + 2 * tid], (double)ss[tid]);
        atomicAdd(&g_stats[set * 34 + 2 * tid + 1], (double)qq[tid]);
    }
}

// ---- finalize BN stats -> fused scale/shift ----
__global__ void k_fin(const float* __restrict__ gamma, const float* __restrict__ beta,
                      double invN, int set) {
    int i = threadIdx.x;
    if (i >= 17) return;
    double s = g_stats[set * 34 + 2 * i];
    double q = g_stats[set * 34 + 2 * i + 1];
    double mean = s * invN;
    double var = q * invN - mean * mean;
    if (var < 0.0) var = 0.0;
    float inv = (float)(1.0 / sqrt(var + 1e-5));
    float sc = gamma[i] * inv;
    float sh = beta[i] - (float)mean * sc;
    if (set == 0) { g_scale1[i] = sc; g_shift1[i] = sh; }
    else          { g_scale2[i] = sc; g_shift2[i] = sh; }
}

// ---- f32x2 GEMM, N=64 (gc layers): C = relu(affine(A) @ W + bias) ----
// RND=1: RNA-round output to tf32 (consumer is the tf32 mma p1 kernel).
template <int AFF, int RND>
__global__ void __launch_bounds__(256)
k_gemm64(const float* __restrict__ A, const float* __restrict__ W,
         const float* __restrict__ bias, float* __restrict__ C,
         int M, int N, int K) {
    __shared__ float As[32 * 130];
    __shared__ float Bs[32 * 128];
    int tid = threadIdx.x;
    int tx = tid & 15, ty = tid >> 4;
    size_t m0 = (size_t)blockIdx.x * 128;

    ull acc[4][4];
#pragma unroll
    for (int j = 0; j < 4; j++) {
        float bv = bias[tx + 16 * j];
        ull pk = pack2(bv, bv);
#pragma unroll
        for (int p = 0; p < 4; p++) acc[p][j] = pk;
    }

    for (int kc = 0; kc < K; kc += 32) {
#pragma unroll
        for (int i = 0; i < 4; i++) {
            int t4 = tid + i * 256;
            int row = t4 >> 3, k4 = t4 & 7;
            float4 v = *(const float4*)(A + (m0 + row) * K + kc + k4 * 4);
            if (AFF != 0) {
                int node = (int)((m0 + row) % 17);
                float sc = (AFF == 1) ? g_scale1[node] : g_scale2[node];
                float sh = (AFF == 1) ? g_shift1[node] : g_shift2[node];
                v.x = fmaf(v.x, sc, sh); v.y = fmaf(v.y, sc, sh);
                v.z = fmaf(v.z, sc, sh); v.w = fmaf(v.w, sc, sh);
            }
            As[(k4 * 4 + 0) * 130 + row] = v.x;
            As[(k4 * 4 + 1) * 130 + row] = v.y;
            As[(k4 * 4 + 2) * 130 + row] = v.z;
            As[(k4 * 4 + 3) * 130 + row] = v.w;
        }
#pragma unroll
        for (int i = 0; i < 2; i++) {
            int t4 = tid + i * 256;
            int k = t4 >> 4, n4 = t4 & 15;
            float4 v = *(const float4*)(W + (size_t)(kc + k) * N + n4 * 4);
            float* bp = &Bs[k * 128 + n4 * 8];
            *(float2*)(bp + 0) = make_float2(v.x, v.x);
            *(float2*)(bp + 2) = make_float2(v.y, v.y);
            *(float2*)(bp + 4) = make_float2(v.z, v.z);
            *(float2*)(bp + 6) = make_float2(v.w, v.w);
        }
        __syncthreads();
#pragma unroll 8
        for (int k = 0; k < 32; k++) {
            ull a0 = *(const ull*)&As[k * 130 + ty * 8 + 0];
            ull a1 = *(const ull*)&As[k * 130 + ty * 8 + 2];
            ull a2 = *(const ull*)&As[k * 130 + ty * 8 + 4];
            ull a3 = *(const ull*)&As[k * 130 + ty * 8 + 6];
            ull b0 = *(const ull*)&Bs[k * 128 + 2 * tx + 0];
            ull b1 = *(const ull*)&Bs[k * 128 + 2 * tx + 32];
            ull b2 = *(const ull*)&Bs[k * 128 + 2 * tx + 64];
            ull b3 = *(const ull*)&Bs[k * 128 + 2 * tx + 96];
            fma2(acc[0][0], a0, b0); fma2(acc[0][1], a0, b1);
            fma2(acc[0][2], a0, b2); fma2(acc[0][3], a0, b3);
            fma2(acc[1][0], a1, b0); fma2(acc[1][1], a1, b1);
            fma2(acc[1][2], a1, b2); fma2(acc[1][3], a1, b3);
            fma2(acc[2][0], a2, b0); fma2(acc[2][1], a2, b1);
            fma2(acc[2][2], a2, b2); fma2(acc[2][3], a2, b3);
            fma2(acc[3][0], a3, b0); fma2(acc[3][1], a3, b1);
            fma2(acc[3][2], a3, b2); fma2(acc[3][3], a3, b3);
        }
        __syncthreads();
    }

#pragma unroll
    for (int p = 0; p < 4; p++) {
        size_t r0 = m0 + ty * 8 + 2 * p;
#pragma unroll
        for (int j = 0; j < 4; j++) {
            float lo, hi;
            unpack2(acc[p][j], lo, hi);
            lo = fmaxf(lo, 0.f); hi = fmaxf(hi, 0.f);
            if (RND) { lo = rna_tf32(lo); hi = rna_tf32(hi); }
            C[r0 * N + tx + 16 * j] = lo;
            C[(r0 + 1) * N + tx + 16 * j] = hi;
        }
    }
}

// ---- p1 via warp-level tf32 mma: g_z = relu(A(B,1088) @ Wp1 + b_p1) ----
// BM=128, BN=128, BK=32; 8 warps in 2(m) x 4(n); warp tile 64x32.
// A pre-rounded to tf32 by gc2 epilogue; Bt = W_p1^T (256x1088) pre-rounded.
// smem per stage: As[128][36] + Bs[128][36] floats; double-buffered cp.async.
#define P1_STAGE_F (128 * 36)
#define P1_SMEM (2 * 2 * P1_STAGE_F * 4)
__global__ void __launch_bounds__(256)
k_p1mma(const float* __restrict__ A, const float* __restrict__ Bt,
        const float* __restrict__ bias, float* __restrict__ C, int B) {
    extern __shared__ float smf[];
    const uint32_t sb = s2u(smf);
    const int tid = threadIdx.x;
    const int w = tid >> 5, lane = tid & 31;
    const int gid = lane >> 2, tig = lane & 3;
    const size_t m0 = (size_t)blockIdx.x * 128;
    const int n0 = blockIdx.y * 128;
    const int wm = (w >> 2) * 64, wn = (w & 3) * 32;

    float acc[4][4][4];
#pragma unroll
    for (int mi = 0; mi < 4; mi++)
#pragma unroll
        for (int ni = 0; ni < 4; ni++)
#pragma unroll
            for (int r = 0; r < 4; r++) acc[mi][ni][r] = 0.f;

    // chunk loader: stage s occupies floats [s*2*STAGE, ...): A then B
    auto load_chunk = [&](int c, int s) {
        uint32_t base = sb + (uint32_t)(s * 2 * P1_STAGE_F) * 4;
        int kc = c * 32;
#pragma unroll
        for (int j = 0; j < 4; j++) {            // A: 128 rows x 8 float4
            int u = tid + j * 256;
            int row = u >> 3, seg = u & 7;
            const float* src = A + (m0 + row) * 1088 + kc + seg * 4;
            uint32_t d = base + (uint32_t)(row * 36 + seg * 4) * 4;
            asm volatile("cp.async.cg.shared.global [%0], [%1], 16;" :: "r"(d), "l"(src) : "memory");
        }
#pragma unroll
        for (int j = 0; j < 4; j++) {            // B: 128 n-rows x 8 float4
            int u = tid + j * 256;
            int row = u >> 3, seg = u & 7;
            const float* src = Bt + (size_t)(n0 + row) * 1088 + kc + seg * 4;
            uint32_t d = base + (uint32_t)(P1_STAGE_F + row * 36 + seg * 4) * 4;
            asm volatile("cp.async.cg.shared.global [%0], [%1], 16;" :: "r"(d), "l"(src) : "memory");
        }
        asm volatile("cp.async.commit_group;" ::: "memory");
    };

    load_chunk(0, 0);
    load_chunk(1, 1);

    for (int c = 0; c < 34; c++) {
        int s = c & 1;
        if (c == 33) asm volatile("cp.async.wait_group 0;" ::: "memory");
        else         asm volatile("cp.async.wait_group 1;" ::: "memory");
        __syncthreads();
        const float* As_s = smf + s * 2 * P1_STAGE_F;
        const float* Bs_s = As_s + P1_STAGE_F;
#pragma unroll
        for (int ks = 0; ks < 4; ks++) {
            uint32_t af[4][4], bf[4][2];
#pragma unroll
            for (int mi = 0; mi < 4; mi++) {
                int rm = wm + mi * 16 + gid;
                af[mi][0] = __float_as_uint(As_s[rm * 36 + ks * 8 + tig]);
                af[mi][1] = __float_as_uint(As_s[(rm + 8) * 36 + ks * 8 + tig]);
                af[mi][2] = __float_as_uint(As_s[rm * 36 + ks * 8 + tig + 4]);
                af[mi][3] = __float_as_uint(As_s[(rm + 8) * 36 + ks * 8 + tig + 4]);
            }
#pragma unroll
            for (int ni = 0; ni < 4; ni++) {
                int rn = wn + ni * 8 + gid;
                bf[ni][0] = __float_as_uint(Bs_s[rn * 36 + ks * 8 + tig]);
                bf[ni][1] = __float_as_uint(Bs_s[rn * 36 + ks * 8 + tig + 4]);
            }
#pragma unroll
            for (int mi = 0; mi < 4; mi++)
#pragma unroll
                for (int ni = 0; ni < 4; ni++) {
                    asm volatile(
                        "mma.sync.aligned.m16n8k8.row.col.f32.tf32.tf32.f32 "
                        "{%0,%1,%2,%3}, {%4,%5,%6,%7}, {%8,%9}, {%0,%1,%2,%3};"
                        : "+f"(acc[mi][ni][0]), "+f"(acc[mi][ni][1]),
                          "+f"(acc[mi][ni][2]), "+f"(acc[mi][ni][3])
                        : "r"(af[mi][0]), "r"(af[mi][1]), "r"(af[mi][2]), "r"(af[mi][3]),
                          "r"(bf[ni][0]), "r"(bf[ni][1]));
                }
        }
        __syncthreads();
        if (c + 2 < 34) load_chunk(c + 2, s);
    }

    // epilogue: + bias, relu
#pragma unroll
    for (int mi = 0; mi < 4; mi++) {
        size_t row = m0 + wm + mi * 16 + gid;
#pragma unroll
        for (int ni = 0; ni < 4; ni++) {
            int col = n0 + wn + ni * 8 + tig * 2;
            float b0 = __ldg(bias + col), b1 = __ldg(bias + col + 1);
            float2 v0, v1;
            v0.x = fmaxf(acc[mi][ni][0] + b0, 0.f);
            v0.y = fmaxf(acc[mi][ni][1] + b1, 0.f);
            v1.x = fmaxf(acc[mi][ni][2] + b0, 0.f);
            v1.y = fmaxf(acc[mi][ni][3] + b1, 0.f);
            *(float2*)(C + row * 256 + col) = v0;
            *(float2*)(C + (row + 8) * 256 + col) = v1;
        }
    }
}

// ---- f32x2 GEMM, BN=128 (p2): thread tile 8x8, BK=16, fused L2 norm ----
template <int RELU, int NORM>
__global__ void __launch_bounds__(256)
k_gemm128(const float* __restrict__ A, const float* __restrict__ W,
          const float* __restrict__ bias, float* __restrict__ C,
          int M, int N, int K) {
    __shared__ float As[16 * 130];
    __shared__ float Bs[16 * 256];
    int tid = threadIdx.x;
    int tx = tid & 15, ty = tid >> 4;
    size_t m0 = (size_t)blockIdx.x * 128;
    int n0 = blockIdx.y * 128;

    ull acc[4][8];
#pragma unroll
    for (int j = 0; j < 8; j++) {
        float bv = bias[n0 + tx + 16 * j];
        ull pk = pack2(bv, bv);
#pragma unroll
        for (int p = 0; p < 4; p++) acc[p][j] = pk;
    }

    for (int kc = 0; kc < K; kc += 16) {
#pragma unroll
        for (int i = 0; i < 2; i++) {
            int t4 = tid + i * 256;
            int row = t4 >> 2, k4 = t4 & 3;
            float4 v = *(const float4*)(A + (m0 + row) * K + kc + k4 * 4);
            As[(k4 * 4 + 0) * 130 + row] = v.x;
            As[(k4 * 4 + 1) * 130 + row] = v.y;
            As[(k4 * 4 + 2) * 130 + row] = v.z;
            As[(k4 * 4 + 3) * 130 + row] = v.w;
        }
#pragma unroll
        for (int i = 0; i < 2; i++) {
            int t4 = tid + i * 256;
            int k = t4 >> 5, n4 = t4 & 31;
            float4 v = *(const float4*)(W + (size_t)(kc + k) * N + n0 + n4 * 4);
            float* bp = &Bs[k * 256 + n4 * 8];
            *(float2*)(bp + 0) = make_float2(v.x, v.x);
            *(float2*)(bp + 2) = make_float2(v.y, v.y);
            *(float2*)(bp + 4) = make_float2(v.z, v.z);
            *(float2*)(bp + 6) = make_float2(v.w, v.w);
        }
        __syncthreads();
#pragma unroll 8
        for (int k = 0; k < 16; k++) {
            ull a0 = *(const ull*)&As[k * 130 + ty * 8 + 0];
            ull a1 = *(const ull*)&As[k * 130 + ty * 8 + 2];
            ull a2 = *(const ull*)&As[k * 130 + ty * 8 + 4];
            ull a3 = *(const ull*)&As[k * 130 + ty * 8 + 6];
#pragma unroll
            for (int j = 0; j < 8; j++) {
                ull b = *(const ull*)&Bs[k * 256 + 2 * tx + 32 * j];
                fma2(acc[0][j], a0, b);
                fma2(acc[1][j], a1, b);
                fma2(acc[2][j], a2, b);
                fma2(acc[3][j], a3, b);
            }
        }
        __syncthreads();
    }

#pragma unroll
    for (int p = 0; p < 4; p++) {
        size_t r0 = m0 + ty * 8 + 2 * p;
        float lo[8], hi[8];
#pragma unroll
        for (int j = 0; j < 8; j++) {
            unpack2(acc[p][j], lo[j], hi[j]);
            if (RELU) { lo[j] = fmaxf(lo[j], 0.f); hi[j] = fmaxf(hi[j], 0.f); }
        }
        if (NORM) {
            float sl = 0.f, sh2 = 0.f;
#pragma unroll
            for (int j = 0; j < 8; j++) {
                sl = fmaf(lo[j], lo[j], sl);
                sh2 = fmaf(hi[j], hi[j], sh2);
            }
#pragma unroll
            for (int off = 8; off > 0; off >>= 1) {
                sl += __shfl_xor_sync(0xffffffffu, sl, off);
                sh2 += __shfl_xor_sync(0xffffffffu, sh2, off);
            }
            float il = 1.f / fmaxf(sqrtf(sl), 1e-12f);
            float ih = 1.f / fmaxf(sqrtf(sh2), 1e-12f);
#pragma unroll
            for (int j = 0; j < 8; j++) {
                C[r0 * N + n0 + tx + 16 * j] = lo[j] * il;
                C[(r0 + 1) * N + n0 + tx + 16 * j] = hi[j] * ih;
            }
        } else {
#pragma unroll
            for (int j = 0; j < 8; j++) {
                C[r0 * N + n0 + tx + 16 * j] = lo[j];
                C[(r0 + 1) * N + n0 + tx + 16 * j] = hi[j];
            }
        }
    }
}

extern "C" void kernel_launch(void* const* d_in, const int* in_sizes, int n_in,
                              void* d_out, int out_size) {
    const float* x      = (const float*)d_in[0];
    const float* W_enc  = (const float*)d_in[1];
    const float* b_enc  = (const float*)d_in[2];
    const float* W_gc1  = (const float*)d_in[3];
    const float* b_gc1  = (const float*)d_in[4];
    const float* W_gc2  = (const float*)d_in[5];
    const float* b_gc2  = (const float*)d_in[6];
    const float* gamma1 = (const float*)d_in[7];
    const float* beta1  = (const float*)d_in[8];
    const float* gamma2 = (const float*)d_in[9];
    const float* beta2  = (const float*)d_in[10];
    const float* W_p1   = (const float*)d_in[11];
    const float* b_p1   = (const float*)d_in[12];
    const float* W_p2   = (const float*)d_in[13];
    const float* b_p2   = (const float*)d_in[14];
    float* out = (float*)d_out;

    // Resolve device addresses of __device__ globals (host shadow != device ptr).
    float *bufA = 0, *bufB = 0, *z = 0, *wp1t = 0;
    cudaGetSymbolAddress((void**)&bufA, g_bufA);
    cudaGetSymbolAddress((void**)&bufB, g_bufB);
    cudaGetSymbolAddress((void**)&z,    g_z);
    cudaGetSymbolAddress((void**)&wp1t, g_wp1t);

    cudaFuncSetAttribute(k_p1mma, cudaFuncAttributeMaxDynamicSharedMemorySize, P1_SMEM);

    int B = in_sizes[0] / 34;        // x is (B,17,2)
    if (B <= 0) return;
    int M17 = B * 17;
    int gF = (B + 7) / 8;
    double invN = 1.0 / ((double)B * 64.0);

    k_zero<<<1, 68>>>();
    k_tr<<<(1088 * 256 + 255) / 256, 256>>>(W_p1, wp1t);
    // enc + agg + BN1 stats -> y1 in bufA
    k_fuse<1><<<gF, 256>>>(x, W_enc, b_enc, bufA, B, 0);
    k_fin<<<1, 32>>>(gamma1, beta1, invN, 0);
    // gc1: h2 = relu(bn1(y1) @ W_gc1 + b) -> bufB
    k_gemm64<1, 0><<<M17 / 128, 256>>>(bufA, W_gc1, b_gc1, bufB, M17, 64, 64);
    // agg(h2) + BN2 stats -> y2 in bufA
    k_fuse<0><<<gF, 256>>>(bufB, 0, 0, bufA, B, 1);
    k_fin<<<1, 32>>>(gamma2, beta2, invN, 1);
    // gc2: pooled = relu(bn2(y2) @ W_gc2 + b), RNA-rounded to tf32 -> bufB (B,1088)
    k_gemm64<2, 1><<<M17 / 128, 256>>>(bufA, W_gc2, b_gc2, bufB, M17, 64, 64);
    // p1 (tf32 mma): z = relu(pooled @ W_p1 + b_p1) -> z (B,256)
    k_p1mma<<<dim3(B / 128, 2), 256, P1_SMEM>>>(bufB, wp1t, b_p1, z, B);
    // p2 + L2 normalize -> out (B,128)
    k_gemm128<0, 1><<<dim3(B / 128, 1), 256>>>(z, W_p2, b_p2, out, B, 128, 256);
}

// round 10
// speedup vs baseline: 2.0402x; 1.3253x over previous
#include <cuda_runtime.h>
#include <math.h>
#include <stdint.h>

#define BMAX 65536

// ---- scratch (allocation-free rule: __device__ globals) ----
__device__ __align__(16) float g_bufA[(size_t)BMAX * 17 * 64];
__device__ __align__(16) float g_bufB[(size_t)BMAX * 17 * 64];
__device__ __align__(16) float g_z[(size_t)BMAX * 256];
__device__ __align__(16) float g_wp1t[256 * 1088];   // W_p1^T (n-major), tf32 RNA-rounded
__device__ __align__(16) float g_wgt1[64 * 64];      // W_gc1^T (n-major), tf32
__device__ __align__(16) float g_wgt2[64 * 64];      // W_gc2^T (n-major), tf32
__device__ double g_stats[68];
__device__ float g_scale1[17], g_shift1[17], g_scale2[17], g_shift2[17];

// ---- adjacency tables (I + A_norm) ----
__constant__ int   c_cnt[17] = {2,0,0,0,0,4,4,2,2,1,1,3,3,2,2,1,1};
__constant__ float c_w[17]   = {0.5f,0.f,0.f,0.f,0.f,0.25f,0.25f,0.5f,0.5f,1.f,1.f,
                                (1.f/3.f),(1.f/3.f),0.5f,0.5f,1.f,1.f};
__constant__ int   c_nb[17][4] = {
    {5,6,0,0},  {0,0,0,0}, {0,0,0,0}, {0,0,0,0}, {0,0,0,0},
    {7,6,11,0}, {8,5,12,0},
    {5,9,0,0},  {6,10,0,0},
    {7,0,0,0},  {8,0,0,0},
    {5,12,13,0},{6,11,14,0},
    {11,15,0,0},{12,16,0,0},
    {13,0,0,0}, {14,0,0,0}
};

// ---- helpers ----
typedef unsigned long long ull;
__device__ __forceinline__ ull pack2(float x, float y) {
    ull r; asm("mov.b64 %0, {%1,%2};" : "=l"(r) : "f"(x), "f"(y)); return r;
}
__device__ __forceinline__ void unpack2(ull v, float &x, float &y) {
    asm("mov.b64 {%0,%1}, %2;" : "=f"(x), "=f"(y) : "l"(v));
}
__device__ __forceinline__ void fma2(ull &d, ull a, ull b) {
    asm("fma.rn.f32x2 %0, %1, %2, %3;" : "=l"(d) : "l"(a), "l"(b), "l"(d));
}
__device__ __forceinline__ float rna_tf32(float v) {
    asm("cvt.rna.tf32.f32 %0, %1;" : "=f"(v) : "f"(v));
    return v;
}
__device__ __forceinline__ uint32_t s2u(const void* p) {
    uint32_t a;
    asm("{ .reg .u64 t; cvta.to.shared.u64 t, %1; cvt.u32.u64 %0, t; }" : "=r"(a) : "l"(p));
    return a;
}
#define MMA_TF32(acc, a0, a1, a2, a3, b0, b1) \
    asm volatile( \
        "mma.sync.aligned.m16n8k8.row.col.f32.tf32.tf32.f32 " \
        "{%0,%1,%2,%3}, {%4,%5,%6,%7}, {%8,%9}, {%0,%1,%2,%3};" \
        : "+f"(acc[0]), "+f"(acc[1]), "+f"(acc[2]), "+f"(acc[3]) \
        : "r"(a0), "r"(a1), "r"(a2), "r"(a3), "r"(b0), "r"(b1))

__global__ void k_zero() {
    if (threadIdx.x < 68) g_stats[threadIdx.x] = 0.0;
}

// ---- transpose W_p1 (1088x256) -> g_wp1t (256x1088), tf32 RNA-rounded ----
__global__ void __launch_bounds__(256)
k_tr(const float* __restrict__ W, float* __restrict__ T) {
    int i = blockIdx.x * 256 + threadIdx.x;
    if (i >= 1088 * 256) return;
    int k = i >> 8, n = i & 255;
    T[(size_t)n * 1088 + k] = rna_tf32(W[i]);
}

// ---- transpose W_gc (64x64) -> (n-major 64x64), tf32 RNA-rounded ----
__global__ void __launch_bounds__(256)
k_trg(const float* __restrict__ W, float* __restrict__ T) {
    int i = blockIdx.x * 256 + threadIdx.x;
    if (i >= 4096) return;
    int k = i >> 6, n = i & 63;
    T[n * 64 + k] = rna_tf32(W[i]);
}

// ---- fused elementwise: (optional encoder) + aggregation + BN stats ----
template <int ENC>
__global__ void __launch_bounds__(256)
k_fuse(const float* __restrict__ src, const float* __restrict__ W,
       const float* __restrict__ bvec, float* __restrict__ ydst, int B, int set) {
    __shared__ float h_sm[8 * 1156];
    __shared__ float ss[17], qq[17];
    int tid = threadIdx.x;
    int s0 = blockIdx.x * 8;
    if (tid < 17) { ss[tid] = 0.f; qq[tid] = 0.f; }

    for (int idx = tid; idx < 272; idx += 256) {
        int n = idx >> 4, c4 = idx & 15;
        float4 w0, w1, bb;
        if (ENC) {
            w0 = *(const float4*)(W + c4 * 4);
            w1 = *(const float4*)(W + 64 + c4 * 4);
            bb = *(const float4*)(bvec + c4 * 4);
        }
#pragma unroll
        for (int s = 0; s < 8; s++) {
            int e = s0 + s;
            if (e >= B) break;
            float4 v;
            if (ENC) {
                float x0 = src[((size_t)e * 17 + n) * 2];
                float x1 = src[((size_t)e * 17 + n) * 2 + 1];
                v.x = fmaxf(fmaf(x0, w0.x, fmaf(x1, w1.x, bb.x)), 0.f);
                v.y = fmaxf(fmaf(x0, w0.y, fmaf(x1, w1.y, bb.y)), 0.f);
                v.z = fmaxf(fmaf(x0, w0.z, fmaf(x1, w1.z, bb.z)), 0.f);
                v.w = fmaxf(fmaf(x0, w0.w, fmaf(x1, w1.w, bb.w)), 0.f);
            } else {
                v = *(const float4*)(src + ((size_t)e * 17 + n) * 64 + c4 * 4);
            }
            *(float4*)&h_sm[s * 1156 + n * 68 + c4 * 4] = v;
        }
    }
    __syncthreads();

    for (int idx = tid; idx < 272; idx += 256) {
        int n = idx >> 4, c4 = idx & 15;
        float w = c_w[n];
        int cnt = c_cnt[n];
        float sp = 0.f, qp = 0.f;
#pragma unroll
        for (int s = 0; s < 8; s++) {
            int e = s0 + s;
            if (e >= B) break;
            float4 acc = *(const float4*)&h_sm[s * 1156 + n * 68 + c4 * 4];
            for (int j = 0; j < cnt; j++) {
                const float4 hb = *(const float4*)&h_sm[s * 1156 + c_nb[n][j] * 68 + c4 * 4];
                acc.x = fmaf(w, hb.x, acc.x);
                acc.y = fmaf(w, hb.y, acc.y);
                acc.z = fmaf(w, hb.z, acc.z);
                acc.w = fmaf(w, hb.w, acc.w);
            }
            *(float4*)(ydst + ((size_t)e * 17 + n) * 64 + c4 * 4) = acc;
            sp += acc.x + acc.y + acc.z + acc.w;
            qp = fmaf(acc.x, acc.x, fmaf(acc.y, acc.y, fmaf(acc.z, acc.z, fmaf(acc.w, acc.w, qp))));
        }
        atomicAdd(&ss[n], sp);
        atomicAdd(&qq[n], qp);
    }
    __syncthreads();
    if (tid < 17) {
        atomicAdd(&g_stats[set * 34 + 2 * tid], (double)ss[tid]);
        atomicAdd(&g_stats[set * 34 + 2 * tid + 1], (double)qq[tid]);
    }
}

// ---- finalize BN stats -> fused scale/shift ----
__global__ void k_fin(const float* __restrict__ gamma, const float* __restrict__ beta,
                      double invN, int set) {
    int i = threadIdx.x;
    if (i >= 17) return;
    double s = g_stats[set * 34 + 2 * i];
    double q = g_stats[set * 34 + 2 * i + 1];
    double mean = s * invN;
    double var = q * invN - mean * mean;
    if (var < 0.0) var = 0.0;
    float inv = (float)(1.0 / sqrt(var + 1e-5));
    float sc = gamma[i] * inv;
    float sh = beta[i] - (float)mean * sc;
    if (set == 0) { g_scale1[i] = sc; g_shift1[i] = sh; }
    else          { g_scale2[i] = sc; g_shift2[i] = sh; }
}

// ---- gc layer via tf32 mma: C = relu(bn_affine(A) @ W + bias) ----
// M%128==0, N=64, K=64. Wt = W^T (n-major, 64x64, pre-rounded tf32).
// BM=128: warp grid 4(m) x 2(n), warp tile 32x32. Single load phase (K=64 fits).
// RND=1: RNA-round output (consumer p1 mma).
#define GC_PAD 68
#define GC_SMEM ((128 * GC_PAD + 64 * GC_PAD) * 4)
template <int AFF, int RND>
__global__ void __launch_bounds__(256)
k_gc(const float* __restrict__ A, const float* __restrict__ Wt,
     const float* __restrict__ bias, float* __restrict__ C, int M) {
    extern __shared__ float smf[];
    float* As = smf;                 // [128][GC_PAD]
    float* Ws = smf + 128 * GC_PAD;  // [64][GC_PAD]
    const int tid = threadIdx.x;
    const int w = tid >> 5, lane = tid & 31;
    const int gid = lane >> 2, tig = lane & 3;
    const size_t m0 = (size_t)blockIdx.x * 128;
    const int wm = (w >> 1) * 32, wn = (w & 1) * 32;

    // load A (affine + tf32 round), 128 rows x 16 float4
#pragma unroll
    for (int j = 0; j < 8; j++) {
        int u = tid + j * 256;
        int row = u >> 4, seg = u & 15;
        float4 v = *(const float4*)(A + (m0 + row) * 64 + seg * 4);
        if (AFF != 0) {
            int node = (int)((m0 + row) % 17);
            float sc = (AFF == 1) ? g_scale1[node] : g_scale2[node];
            float sh = (AFF == 1) ? g_shift1[node] : g_shift2[node];
            v.x = fmaf(v.x, sc, sh); v.y = fmaf(v.y, sc, sh);
            v.z = fmaf(v.z, sc, sh); v.w = fmaf(v.w, sc, sh);
        }
        float* ap = &As[row * GC_PAD + seg * 4];
        ap[0] = rna_tf32(v.x); ap[1] = rna_tf32(v.y);
        ap[2] = rna_tf32(v.z); ap[3] = rna_tf32(v.w);
    }
    // load Wt (already tf32), 64 rows x 16 float4
#pragma unroll
    for (int j = 0; j < 4; j++) {
        int u = tid + j * 256;
        int row = u >> 4, seg = u & 15;
        *(float4*)&Ws[row * GC_PAD + seg * 4] = *(const float4*)(Wt + row * 64 + seg * 4);
    }
    __syncthreads();

    float acc[2][4][4];
#pragma unroll
    for (int mi = 0; mi < 2; mi++)
#pragma unroll
        for (int ni = 0; ni < 4; ni++)
#pragma unroll
            for (int r = 0; r < 4; r++) acc[mi][ni][r] = 0.f;

#pragma unroll
    for (int ks = 0; ks < 8; ks++) {
        uint32_t af[2][4], bf[4][2];
#pragma unroll
        for (int mi = 0; mi < 2; mi++) {
            int rm = wm + mi * 16 + gid;
            af[mi][0] = __float_as_uint(As[rm * GC_PAD + ks * 8 + tig]);
            af[mi][1] = __float_as_uint(As[(rm + 8) * GC_PAD + ks * 8 + tig]);
            af[mi][2] = __float_as_uint(As[rm * GC_PAD + ks * 8 + tig + 4]);
            af[mi][3] = __float_as_uint(As[(rm + 8) * GC_PAD + ks * 8 + tig + 4]);
        }
#pragma unroll
        for (int ni = 0; ni < 4; ni++) {
            int rn = wn + ni * 8 + gid;
            bf[ni][0] = __float_as_uint(Ws[rn * GC_PAD + ks * 8 + tig]);
            bf[ni][1] = __float_as_uint(Ws[rn * GC_PAD + ks * 8 + tig + 4]);
        }
#pragma unroll
        for (int mi = 0; mi < 2; mi++)
#pragma unroll
            for (int ni = 0; ni < 4; ni++)
                MMA_TF32(acc[mi][ni], af[mi][0], af[mi][1], af[mi][2], af[mi][3],
                         bf[ni][0], bf[ni][1]);
    }

    // epilogue: +bias, relu, optional tf32 round
#pragma unroll
    for (int mi = 0; mi < 2; mi++) {
        size_t row = m0 + wm + mi * 16 + gid;
#pragma unroll
        for (int ni = 0; ni < 4; ni++) {
            int col = wn + ni * 8 + tig * 2;
            float b0 = __ldg(bias + col), b1 = __ldg(bias + col + 1);
            float2 v0, v1;
            v0.x = fmaxf(acc[mi][ni][0] + b0, 0.f);
            v0.y = fmaxf(acc[mi][ni][1] + b1, 0.f);
            v1.x = fmaxf(acc[mi][ni][2] + b0, 0.f);
            v1.y = fmaxf(acc[mi][ni][3] + b1, 0.f);
            if (RND) {
                v0.x = rna_tf32(v0.x); v0.y = rna_tf32(v0.y);
                v1.x = rna_tf32(v1.x); v1.y = rna_tf32(v1.y);
            }
            *(float2*)(C + row * 64 + col) = v0;
            *(float2*)(C + (row + 8) * 64 + col) = v1;
        }
    }
}

// ---- p1 via warp-level tf32 mma: g_z = relu(A(B,1088) @ Wp1 + b_p1) ----
#define P1_STAGE_F (128 * 36)
#define P1_SMEM (2 * 2 * P1_STAGE_F * 4)
__global__ void __launch_bounds__(256)
k_p1mma(const float* __restrict__ A, const float* __restrict__ Bt,
        const float* __restrict__ bias, float* __restrict__ C, int B) {
    extern __shared__ float smf[];
    const uint32_t sb = s2u(smf);
    const int tid = threadIdx.x;
    const int w = tid >> 5, lane = tid & 31;
    const int gid = lane >> 2, tig = lane & 3;
    const size_t m0 = (size_t)blockIdx.x * 128;
    const int n0 = blockIdx.y * 128;
    const int wm = (w >> 2) * 64, wn = (w & 3) * 32;

    float acc[4][4][4];
#pragma unroll
    for (int mi = 0; mi < 4; mi++)
#pragma unroll
        for (int ni = 0; ni < 4; ni++)
#pragma unroll
            for (int r = 0; r < 4; r++) acc[mi][ni][r] = 0.f;

    auto load_chunk = [&](int c, int s) {
        uint32_t base = sb + (uint32_t)(s * 2 * P1_STAGE_F) * 4;
        int kc = c * 32;
#pragma unroll
        for (int j = 0; j < 4; j++) {
            int u = tid + j * 256;
            int row = u >> 3, seg = u & 7;
            const float* src = A + (m0 + row) * 1088 + kc + seg * 4;
            uint32_t d = base + (uint32_t)(row * 36 + seg * 4) * 4;
            asm volatile("cp.async.cg.shared.global [%0], [%1], 16;" :: "r"(d), "l"(src) : "memory");
        }
#pragma unroll
        for (int j = 0; j < 4; j++) {
            int u = tid + j * 256;
            int row = u >> 3, seg = u & 7;
            const float* src = Bt + (size_t)(n0 + row) * 1088 + kc + seg * 4;
            uint32_t d = base + (uint32_t)(P1_STAGE_F + row * 36 + seg * 4) * 4;
            asm volatile("cp.async.cg.shared.global [%0], [%1], 16;" :: "r"(d), "l"(src) : "memory");
        }
        asm volatile("cp.async.commit_group;" ::: "memory");
    };

    load_chunk(0, 0);
    load_chunk(1, 1);

    for (int c = 0; c < 34; c++) {
        int s = c & 1;
        if (c == 33) asm volatile("cp.async.wait_group 0;" ::: "memory");
        else         asm volatile("cp.async.wait_group 1;" ::: "memory");
        __syncthreads();
        const float* As_s = smf + s * 2 * P1_STAGE_F;
        const float* Bs_s = As_s + P1_STAGE_F;
#pragma unroll
        for (int ks = 0; ks < 4; ks++) {
            uint32_t af[4][4], bf[4][2];
#pragma unroll
            for (int mi = 0; mi < 4; mi++) {
                int rm = wm + mi * 16 + gid;
                af[mi][0] = __float_as_uint(As_s[rm * 36 + ks * 8 + tig]);
                af[mi][1] = __float_as_uint(As_s[(rm + 8) * 36 + ks * 8 + tig]);
                af[mi][2] = __float_as_uint(As_s[rm * 36 + ks * 8 + tig + 4]);
                af[mi][3] = __float_as_uint(As_s[(rm + 8) * 36 + ks * 8 + tig + 4]);
            }
#pragma unroll
            for (int ni = 0; ni < 4; ni++) {
                int rn = wn + ni * 8 + gid;
                bf[ni][0] = __float_as_uint(Bs_s[rn * 36 + ks * 8 + tig]);
                bf[ni][1] = __float_as_uint(Bs_s[rn * 36 + ks * 8 + tig + 4]);
            }
#pragma unroll
            for (int mi = 0; mi < 4; mi++)
#pragma unroll
                for (int ni = 0; ni < 4; ni++)
                    MMA_TF32(acc[mi][ni], af[mi][0], af[mi][1], af[mi][2], af[mi][3],
                             bf[ni][0], bf[ni][1]);
        }
        __syncthreads();
        if (c + 2 < 34) load_chunk(c + 2, s);
    }

#pragma unroll
    for (int mi = 0; mi < 4; mi++) {
        size_t row = m0 + wm + mi * 16 + gid;
#pragma unroll
        for (int ni = 0; ni < 4; ni++) {
            int col = n0 + wn + ni * 8 + tig * 2;
            float b0 = __ldg(bias + col), b1 = __ldg(bias + col + 1);
            float2 v0, v1;
            v0.x = fmaxf(acc[mi][ni][0] + b0, 0.f);
            v0.y = fmaxf(acc[mi][ni][1] + b1, 0.f);
            v1.x = fmaxf(acc[mi][ni][2] + b0, 0.f);
            v1.y = fmaxf(acc[mi][ni][3] + b1, 0.f);
            *(float2*)(C + row * 256 + col) = v0;
            *(float2*)(C + (row + 8) * 256 + col) = v1;
        }
    }
}

// ---- f32x2 GEMM, BN=128 (p2): thread tile 8x8, BK=16, fused L2 norm ----
template <int RELU, int NORM>
__global__ void __launch_bounds__(256)
k_gemm128(const float* __restrict__ A, const float* __restrict__ W,
          const float* __restrict__ bias, float* __restrict__ C,
          int M, int N, int K) {
    __shared__ float As[16 * 130];
    __shared__ float Bs[16 * 256];
    int tid = threadIdx.x;
    int tx = tid & 15, ty = tid >> 4;
    size_t m0 = (size_t)blockIdx.x * 128;
    int n0 = blockIdx.y * 128;

    ull acc[4][8];
#pragma unroll
    for (int j = 0; j < 8; j++) {
        float bv = bias[n0 + tx + 16 * j];
        ull pk = pack2(bv, bv);
#pragma unroll
        for (int p = 0; p < 4; p++) acc[p][j] = pk;
    }

    for (int kc = 0; kc < K; kc += 16) {
#pragma unroll
        for (int i = 0; i < 2; i++) {
            int t4 = tid + i * 256;
            int row = t4 >> 2, k4 = t4 & 3;
            float4 v = *(const float4*)(A + (m0 + row) * K + kc + k4 * 4);
            As[(k4 * 4 + 0) * 130 + row] = v.x;
            As[(k4 * 4 + 1) * 130 + row] = v.y;
            As[(k4 * 4 + 2) * 130 + row] = v.z;
            As[(k4 * 4 + 3) * 130 + row] = v.w;
        }
#pragma unroll
        for (int i = 0; i < 2; i++) {
            int t4 = tid + i * 256;
            int k = t4 >> 5, n4 = t4 & 31;
            float4 v = *(const float4*)(W + (size_t)(kc + k) * N + n0 + n4 * 4);
            float* bp = &Bs[k * 256 + n4 * 8];
            *(float2*)(bp + 0) = make_float2(v.x, v.x);
            *(float2*)(bp + 2) = make_float2(v.y, v.y);
            *(float2*)(bp + 4) = make_float2(v.z, v.z);
            *(float2*)(bp + 6) = make_float2(v.w, v.w);
        }
        __syncthreads();
#pragma unroll 8
        for (int k = 0; k < 16; k++) {
            ull a0 = *(const ull*)&As[k * 130 + ty * 8 + 0];
            ull a1 = *(const ull*)&As[k * 130 + ty * 8 + 2];
            ull a2 = *(const ull*)&As[k * 130 + ty * 8 + 4];
            ull a3 = *(const ull*)&As[k * 130 + ty * 8 + 6];
#pragma unroll
            for (int j = 0; j < 8; j++) {
                ull b = *(const ull*)&Bs[k * 256 + 2 * tx + 32 * j];
                fma2(acc[0][j], a0, b);
                fma2(acc[1][j], a1, b);
                fma2(acc[2][j], a2, b);
                fma2(acc[3][j], a3, b);
            }
        }
        __syncthreads();
    }

#pragma unroll
    for (int p = 0; p < 4; p++) {
        size_t r0 = m0 + ty * 8 + 2 * p;
        float lo[8], hi[8];
#pragma unroll
        for (int j = 0; j < 8; j++) {
            unpack2(acc[p][j], lo[j], hi[j]);
            if (RELU) { lo[j] = fmaxf(lo[j], 0.f); hi[j] = fmaxf(hi[j], 0.f); }
        }
        if (NORM) {
            float sl = 0.f, sh2 = 0.f;
#pragma unroll
            for (int j = 0; j < 8; j++) {
                sl = fmaf(lo[j], lo[j], sl);
                sh2 = fmaf(hi[j], hi[j], sh2);
            }
#pragma unroll
            for (int off = 8; off > 0; off >>= 1) {
                sl += __shfl_xor_sync(0xffffffffu, sl, off);
                sh2 += __shfl_xor_sync(0xffffffffu, sh2, off);
            }
            float il = 1.f / fmaxf(sqrtf(sl), 1e-12f);
            float ih = 1.f / fmaxf(sqrtf(sh2), 1e-12f);
#pragma unroll
            for (int j = 0; j < 8; j++) {
                C[r0 * N + n0 + tx + 16 * j] = lo[j] * il;
                C[(r0 + 1) * N + n0 + tx + 16 * j] = hi[j] * ih;
            }
        } else {
#pragma unroll
            for (int j = 0; j < 8; j++) {
                C[r0 * N + n0 + tx + 16 * j] = lo[j];
                C[(r0 + 1) * N + n0 + tx + 16 * j] = hi[j];
            }
        }
    }
}

extern "C" void kernel_launch(void* const* d_in, const int* in_sizes, int n_in,
                              void* d_out, int out_size) {
    const float* x      = (const float*)d_in[0];
    const float* W_enc  = (const float*)d_in[1];
    const float* b_enc  = (const float*)d_in[2];
    const float* W_gc1  = (const float*)d_in[3];
    const float* b_gc1  = (const float*)d_in[4];
    const float* W_gc2  = (const float*)d_in[5];
    const float* b_gc2  = (const float*)d_in[6];
    const float* gamma1 = (const float*)d_in[7];
    const float* beta1  = (const float*)d_in[8];
    const float* gamma2 = (const float*)d_in[9];
    const float* beta2  = (const float*)d_in[10];
    const float* W_p1   = (const float*)d_in[11];
    const float* b_p1   = (const float*)d_in[12];
    const float* W_p2   = (const float*)d_in[13];
    const float* b_p2   = (const float*)d_in[14];
    float* out = (float*)d_out;

    // Resolve device addresses of __device__ globals (host shadow != device ptr).
    float *bufA = 0, *bufB = 0, *z = 0, *wp1t = 0, *wgt1 = 0, *wgt2 = 0;
    cudaGetSymbolAddress((void**)&bufA, g_bufA);
    cudaGetSymbolAddress((void**)&bufB, g_bufB);
    cudaGetSymbolAddress((void**)&z,    g_z);
    cudaGetSymbolAddress((void**)&wp1t, g_wp1t);
    cudaGetSymbolAddress((void**)&wgt1, g_wgt1);
    cudaGetSymbolAddress((void**)&wgt2, g_wgt2);

    cudaFuncSetAttribute(k_p1mma, cudaFuncAttributeMaxDynamicSharedMemorySize, P1_SMEM);
    cudaFuncSetAttribute(k_gc<1, 0>, cudaFuncAttributeMaxDynamicSharedMemorySize, GC_SMEM);
    cudaFuncSetAttribute(k_gc<2, 1>, cudaFuncAttributeMaxDynamicSharedMemorySize, GC_SMEM);

    int B = in_sizes[0] / 34;        // x is (B,17,2)
    if (B <= 0) return;
    int M17 = B * 17;
    int gF = (B + 7) / 8;
    double invN = 1.0 / ((double)B * 64.0);

    k_zero<<<1, 68>>>();
    k_tr<<<(1088 * 256 + 255) / 256, 256>>>(W_p1, wp1t);
    k_trg<<<16, 256>>>(W_gc1, wgt1);
    k_trg<<<16, 256>>>(W_gc2, wgt2);
    // enc + agg + BN1 stats -> y1 in bufA
    k_fuse<1><<<gF, 256>>>(x, W_enc, b_enc, bufA, B, 0);
    k_fin<<<1, 32>>>(gamma1, beta1, invN, 0);
    // gc1 (tf32 mma): h2 = relu(bn1(y1) @ W_gc1 + b) -> bufB
    k_gc<1, 0><<<M17 / 128, 256, GC_SMEM>>>(bufA, wgt1, b_gc1, bufB, M17);
    // agg(h2) + BN2 stats -> y2 in bufA
    k_fuse<0><<<gF, 256>>>(bufB, 0, 0, bufA, B, 1);
    k_fin<<<1, 32>>>(gamma2, beta2, invN, 1);
    // gc2 (tf32 mma): pooled = relu(bn2(y2) @ W_gc2 + b), tf32-rounded -> bufB
    k_gc<2, 1><<<M17 / 128, 256, GC_SMEM>>>(bufA, wgt2, b_gc2, bufB, M17);
    // p1 (tf32 mma): z = relu(pooled @ W_p1 + b_p1) -> z (B,256)
    k_p1mma<<<dim3(B / 128, 2), 256, P1_SMEM>>>(bufB, wp1t, b_p1, z, B);
    // p2 + L2 normalize -> out (B,128)
    k_gemm128<0, 1><<<dim3(B / 128, 1), 256>>>(z, W_p2, b_p2, out, B, 128, 256);
}